// round 14
// baseline (speedup 1.0000x reference)
#include <cuda_runtime.h>
#include <cuda_fp16.h>
#include <cstdint>
#include <cstddef>

// ---------------- problem constants ----------------
#define B_SZ   8
#define N_TOK  1024
#define C_DIM  768
#define H_NUM  12
#define D_HEAD 64
#define SCALE_Q 0.125f   // 64^-0.5

// ---------------- scratch (device globals; no cudaMalloc allowed) ----------------
__device__ __half g_qkv [(size_t)B_SZ * N_TOK * 3 * C_DIM];   // fp16, Q pre-scaled
__device__ __half g_attn[(size_t)B_SZ * N_TOK * C_DIM];       // fp16 attention out
__device__ __half g_xh  [(size_t)B_SZ * N_TOK * C_DIM];       // x -> fp16
__device__ __half g_wqkvT[(size_t)3 * C_DIM * C_DIM];         // w_qkv^T [2304][768] fp16
__device__ __half g_wprojT[(size_t)C_DIM * C_DIM];            // w_proj^T [768][768] fp16

// ---------------- helpers ----------------
__device__ __forceinline__ void mma_f16(float* d, const uint32_t* a, const uint32_t* b) {
    asm volatile(
        "mma.sync.aligned.m16n8k16.row.col.f32.f16.f16.f32 "
        "{%0,%1,%2,%3}, {%4,%5,%6,%7}, {%8,%9}, {%0,%1,%2,%3};"
        : "+f"(d[0]), "+f"(d[1]), "+f"(d[2]), "+f"(d[3])
        : "r"(a[0]), "r"(a[1]), "r"(a[2]), "r"(a[3]),
          "r"(b[0]), "r"(b[1]));
}

__device__ __forceinline__ void ldsm_x4(uint32_t* r, const void* p) {
    uint32_t addr = (uint32_t)__cvta_generic_to_shared(p);
    asm volatile(
        "ldmatrix.sync.aligned.m8n8.x4.shared.b16 {%0,%1,%2,%3}, [%4];"
        : "=r"(r[0]), "=r"(r[1]), "=r"(r[2]), "=r"(r[3]) : "r"(addr));
}

__device__ __forceinline__ void ldsm_x4_trans(uint32_t* r, const void* p) {
    uint32_t addr = (uint32_t)__cvta_generic_to_shared(p);
    asm volatile(
        "ldmatrix.sync.aligned.m8n8.x4.trans.shared.b16 {%0,%1,%2,%3}, [%4];"
        : "=r"(r[0]), "=r"(r[1]), "=r"(r[2]), "=r"(r[3]) : "r"(addr));
}

__device__ __forceinline__ void cp_async16(void* smem_dst, const void* gmem_src) {
    uint32_t a = (uint32_t)__cvta_generic_to_shared(smem_dst);
    asm volatile("cp.async.cg.shared.global [%0], [%1], 16;" :: "r"(a), "l"(gmem_src));
}
#define CP_COMMIT()  asm volatile("cp.async.commit_group;")
#define CP_WAIT(n)   asm volatile("cp.async.wait_group %0;" :: "n"(n))

__device__ __forceinline__ uint32_t packh2(float a, float b) {
    __half2 h = __floats2half2_rn(a, b);
    return *(uint32_t*)&h;
}

// SW128 swizzle on byte offsets (rows of 128B)
__device__ __forceinline__ char* swz(char* base, int byteoff) {
    return base + (byteoff ^ ((byteoff >> 3) & 0x70));
}

// ============================================================
// fused pre-pass: x->fp16 | transpose w_qkv | transpose w_proj
// ============================================================
#define PP_XBLKS  ((B_SZ * N_TOK * C_DIM / 4 + 255) / 256)
#define PP_WQBLKS ((3 * C_DIM / 32) * (C_DIM / 32))
#define PP_WPBLKS ((C_DIM / 32) * (C_DIM / 32))

__global__ __launch_bounds__(256) void prepass_kernel(
    const float* __restrict__ x,     __half* __restrict__ xh,
    const float* __restrict__ wqkv,  __half* __restrict__ wqkvT,
    const float* __restrict__ wproj, __half* __restrict__ wprojT)
{
    const int blk = blockIdx.x;
    const int tid = threadIdx.x;
    if (blk < PP_XBLKS) {
        const int i = blk * 256 + tid;
        float4 v = ((const float4*)x)[i];
        __half2* o = (__half2*)(xh + (size_t)i * 4);
        o[0] = __floats2half2_rn(v.x, v.y);
        o[1] = __floats2half2_rn(v.z, v.w);
        return;
    }
    __shared__ float tile[32][33];
    const float* in;
    __half* outp;
    int R, Ncols, bi;
    if (blk < PP_XBLKS + PP_WQBLKS) {
        bi = blk - PP_XBLKS; in = wqkv; outp = wqkvT; R = C_DIM; Ncols = 3 * C_DIM;
    } else {
        bi = blk - PP_XBLKS - PP_WQBLKS; in = wproj; outp = wprojT; R = C_DIM; Ncols = C_DIM;
    }
    const int nbx = Ncols / 32;
    const int bx = (bi % nbx) * 32, by = (bi / nbx) * 32;
    const int tx = tid & 31, ty = tid >> 5;
#pragma unroll
    for (int j = 0; j < 32; j += 8)
        tile[ty + j][tx] = in[(size_t)(by + ty + j) * Ncols + bx + tx];
    __syncthreads();
#pragma unroll
    for (int j = 0; j < 32; j += 8)
        outp[(size_t)(bx + ty + j) * R + by + tx] = __float2half_rn(tile[tx][ty + j]);
}

// ============================================================
// GEMM1: 256x128x32 CTA tile, 256 threads / 8 warps,
// warp tile 64x64 (warps 4M x 2N), 4-stage cp.async, 1 CTA/SM.
// Halves B-operand L2 re-reads vs 128x128 tiles.
// fp16 out, cols < C_DIM scaled by SCALE_Q.
// ============================================================
#define GPITCH 40
#define G1STAGES 4
#define G1_SMEM_BYTES (G1STAGES * (256 + 128) * GPITCH * 2)   // 122880

__global__ __launch_bounds__(256, 1) void gemm1_f16(
    const __half* __restrict__ A, const __half* __restrict__ BT,
    __half* __restrict__ Cout, int M, int N, int K)
{
    extern __shared__ __half smh[];
    __half (*As)[256][GPITCH] = (__half(*)[256][GPITCH])(smh);
    __half (*Bs)[128][GPITCH] = (__half(*)[128][GPITCH])(smh + G1STAGES * 256 * GPITCH);

    const int tid  = threadIdx.x;
    const int wid  = tid >> 5;
    const int lane = tid & 31;
    const int grp  = lane >> 2;
    const int qd   = lane & 3;

    const int brow = blockIdx.y * 256;
    const int bcol = blockIdx.x * 128;
    const int m_base = (wid & 3) * 64;   // 4 warps along M
    const int n_base = (wid >> 2) * 64;  // 2 warps along N

    float acc[4][8][4];
#pragma unroll
    for (int i = 0; i < 4; i++)
#pragma unroll
        for (int j = 0; j < 8; j++)
#pragma unroll
            for (int t = 0; t < 4; t++) acc[i][j][t] = 0.f;

    // per stage: A = 256 rows x 2 chunks = 512 chunks? No: 256 rows x 32 cols
    //   = 256*32*2B = 16KB = 1024 chunks over 256 thr = 4 each
    // B = 128 rows = 512 chunks = 2 each
    auto load_tile = [&](int t, int s) {
        const int k0 = t * 32;
#pragma unroll
        for (int i = 0; i < 4; i++) {
            const int ch = tid + i * 256;
            const int r = ch >> 2, co = (ch & 3) * 8;
            cp_async16(&As[s][r][co], &A[(size_t)(brow + r) * K + k0 + co]);
        }
#pragma unroll
        for (int i = 0; i < 2; i++) {
            const int ch = tid + i * 256;
            const int r = ch >> 2, co = (ch & 3) * 8;
            cp_async16(&Bs[s][r][co], &BT[(size_t)(bcol + r) * K + k0 + co]);
        }
    };

    const int T = K / 32;
#pragma unroll
    for (int t = 0; t < G1STAGES - 1; t++) {
        if (t < T) load_tile(t, t);
        CP_COMMIT();
    }

    int buf = 0, lbuf = G1STAGES - 1;
    for (int t = 0; t < T; t++) {
        CP_WAIT(G1STAGES - 2);
        __syncthreads();
        if (t + G1STAGES - 1 < T) load_tile(t + G1STAGES - 1, lbuf);
        CP_COMMIT();

#pragma unroll
        for (int ks = 0; ks < 32; ks += 16) {
            uint32_t af[4][4];
#pragma unroll
            for (int mt = 0; mt < 4; mt++)
                ldsm_x4(af[mt], &As[buf][m_base + mt * 16 + (lane & 15)][ks + ((lane >> 4) << 3)]);
            uint32_t bf[4][4];
#pragma unroll
            for (int ntp = 0; ntp < 4; ntp++)
                ldsm_x4(bf[ntp], &Bs[buf][n_base + ntp * 16 + ((lane >> 4) << 3) + (lane & 7)]
                                         [ks + (((lane >> 3) & 1) << 3)]);
#pragma unroll
            for (int nt = 0; nt < 8; nt++) {
                const uint32_t* bb = &bf[nt >> 1][(nt & 1) * 2];
#pragma unroll
                for (int mt = 0; mt < 4; mt++)
                    mma_f16(acc[mt][nt], af[mt], bb);
            }
        }
        if (++buf == G1STAGES) buf = 0;
        if (++lbuf == G1STAGES) lbuf = 0;
    }

#pragma unroll
    for (int mt = 0; mt < 4; mt++) {
        const int r1 = brow + m_base + mt * 16 + grp;
        const int r2 = r1 + 8;
#pragma unroll
        for (int nt = 0; nt < 8; nt++) {
            const int c = bcol + n_base + nt * 8 + 2 * qd;
            const float s = (c < C_DIM) ? SCALE_Q : 1.f;
            *(__half2*)&Cout[(size_t)r1 * N + c] =
                __floats2half2_rn(acc[mt][nt][0] * s, acc[mt][nt][1] * s);
            *(__half2*)&Cout[(size_t)r2 * N + c] =
                __floats2half2_rn(acc[mt][nt][2] * s, acc[mt][nt][3] * s);
        }
    }
}

// ============================================================
// GEMM2: 128x128x32 tile, 256 threads / 8 warps, warp 64x32,
// 5-stage cp.async, 2 CTAs/SM. fp32 out + bias. (measured best)
// ============================================================
#define G2STAGES 5
#define G2_SMEM_BYTES (G2STAGES * 2 * 128 * GPITCH * 2)   // 102400

__global__ __launch_bounds__(256, 2) void gemm2_f16(
    const __half* __restrict__ A, const __half* __restrict__ BT,
    const float* __restrict__ bias, float* __restrict__ C,
    int M, int N, int K)
{
    extern __shared__ __half smh[];
    __half (*As)[128][GPITCH] = (__half(*)[128][GPITCH])(smh);
    __half (*Bs)[128][GPITCH] = (__half(*)[128][GPITCH])(smh + G2STAGES * 128 * GPITCH);

    const int tid  = threadIdx.x;
    const int wid  = tid >> 5;
    const int lane = tid & 31;
    const int grp  = lane >> 2;
    const int qd   = lane & 3;

    const int brow = blockIdx.y * 128;
    const int bcol = blockIdx.x * 128;
    const int m_base = (wid & 1) * 64;
    const int n_base = (wid >> 1) * 32;

    float acc[4][4][4];
#pragma unroll
    for (int i = 0; i < 4; i++)
#pragma unroll
        for (int j = 0; j < 4; j++)
#pragma unroll
            for (int t = 0; t < 4; t++) acc[i][j][t] = 0.f;

    auto load_tile = [&](int t, int s) {
        const int k0 = t * 32;
#pragma unroll
        for (int i = 0; i < 2; i++) {
            const int ch = tid + i * 256;
            const int r = ch >> 2, co = (ch & 3) * 8;
            cp_async16(&As[s][r][co], &A [(size_t)(brow + r) * K + k0 + co]);
            cp_async16(&Bs[s][r][co], &BT[(size_t)(bcol + r) * K + k0 + co]);
        }
    };

    const int T = K / 32;
#pragma unroll
    for (int t = 0; t < G2STAGES - 1; t++) {
        if (t < T) load_tile(t, t);
        CP_COMMIT();
    }

    int buf = 0, lbuf = (G2STAGES - 1) % G2STAGES;
    for (int t = 0; t < T; t++) {
        CP_WAIT(G2STAGES - 2);
        __syncthreads();
        if (t + G2STAGES - 1 < T) load_tile(t + G2STAGES - 1, lbuf);
        CP_COMMIT();

#pragma unroll
        for (int ks = 0; ks < 32; ks += 16) {
            uint32_t af[4][4];
#pragma unroll
            for (int mt = 0; mt < 4; mt++)
                ldsm_x4(af[mt], &As[buf][m_base + mt * 16 + (lane & 15)][ks + ((lane >> 4) << 3)]);
            uint32_t bf[2][4];
#pragma unroll
            for (int ntp = 0; ntp < 2; ntp++)
                ldsm_x4(bf[ntp], &Bs[buf][n_base + ntp * 16 + ((lane >> 4) << 3) + (lane & 7)]
                                         [ks + (((lane >> 3) & 1) << 3)]);
#pragma unroll
            for (int nt = 0; nt < 4; nt++) {
                const uint32_t* bb = &bf[nt >> 1][(nt & 1) * 2];
#pragma unroll
                for (int mt = 0; mt < 4; mt++)
                    mma_f16(acc[mt][nt], af[mt], bb);
            }
        }
        if (++buf == G2STAGES) buf = 0;
        if (++lbuf == G2STAGES) lbuf = 0;
    }

#pragma unroll
    for (int mt = 0; mt < 4; mt++) {
        const int r1 = brow + m_base + mt * 16 + grp;
        const int r2 = r1 + 8;
#pragma unroll
        for (int nt = 0; nt < 4; nt++) {
            const int c = bcol + n_base + nt * 8 + 2 * qd;
            const float b0 = __ldg(&bias[c]), b1 = __ldg(&bias[c + 1]);
            *(float2*)&C[(size_t)r1 * N + c] =
                make_float2(acc[mt][nt][0] + b0, acc[mt][nt][1] + b1);
            *(float2*)&C[(size_t)r2 * N + c] =
                make_float2(acc[mt][nt][2] + b0, acc[mt][nt][3] + b1);
        }
    }
}

// ============================================================
// Fused Taylor attention — R9 config (measured best):
// 128 threads (4 warps), Q tile 64, KV tile 128 double-buffered,
// SW128 smem, Q aliased onto KV buf1, 3 CTAs/SM, register repack.
// g(s) = (s+1)^2 + 1 (= 2*f; scale cancels in normalization).
// ============================================================
#define QROWS 64
#define KTILE 128
#define TILE_B 16384
#define ATTN_SMEM_BYTES (4 * TILE_B)

__global__ __launch_bounds__(128, 3) void attn_f16(
    const __half* __restrict__ qkv, __half* __restrict__ out)
{
    extern __shared__ char smc[];
    char* const kbuf[2] = { smc,          smc + 2 * TILE_B };
    char* const vbuf[2] = { smc + TILE_B, smc + 3 * TILE_B };
    char* const qbuf    = smc + 2 * TILE_B;   // alias: K1 region

    const int tid  = threadIdx.x;
    const int wid  = tid >> 5;
    const int lane = tid & 31;
    const int grp  = lane >> 2;
    const int qd   = lane & 3;

    const int b    = blockIdx.y / H_NUM;
    const int h    = blockIdx.y % H_NUM;
    const int row0 = blockIdx.x * QROWS;

    const int pm0 = wid * 16;   // warp's 16 Q-rows

    auto load_kv = [&](int m0, int s) {
#pragma unroll
        for (int l = 0; l < 8; l++) {
            const int ch = tid + l * 128;
            const int r = ch >> 3, cb = (ch & 7) * 16;
            const size_t nb = (size_t)(b * N_TOK + m0 + r) * 3;
            cp_async16(swz(kbuf[s], r * 128 + cb), &qkv[(nb + 1) * C_DIM + h * D_HEAD + cb / 2]);
            cp_async16(swz(vbuf[s], r * 128 + cb), &qkv[(nb + 2) * C_DIM + h * D_HEAD + cb / 2]);
        }
    };

    // prologue: Q (into qbuf = K1) + KV(0)
#pragma unroll
    for (int l = 0; l < 4; l++) {
        const int ch = tid + l * 128;
        const int r = ch >> 3, cb = (ch & 7) * 16;
        cp_async16(swz(qbuf, r * 128 + cb),
                   &qkv[((size_t)(b * N_TOK + row0 + r) * 3) * C_DIM + h * D_HEAD + cb / 2]);
    }
    load_kv(0, 0);
    CP_COMMIT();
    CP_WAIT(0);
    __syncthreads();

    // hoist Q fragments, then free qbuf for KV buf1
    uint32_t aq[4][4];
#pragma unroll
    for (int kk4 = 0; kk4 < 4; kk4++)
        ldsm_x4(aq[kk4], swz(qbuf, (pm0 + (lane & 15)) * 128
                                   + (kk4 * 16 + ((lane >> 4) << 3)) * 2));
    __syncthreads();   // all warps hold aq before buf1 is overwritten

    float acc_o[8][4];
#pragma unroll
    for (int i = 0; i < 8; i++)
#pragma unroll
        for (int t = 0; t < 4; t++) acc_o[i][t] = 0.f;
    float dn0a = 0.f, dn0b = 0.f, dn1a = 0.f, dn1b = 0.f;

    const int NT = N_TOK / KTILE;   // 8
    for (int t = 0; t < NT; t++) {
        const int buf = t & 1;
        if (t > 0) {
            CP_WAIT(0);
            __syncthreads();
        }
        if (t + 1 < NT) load_kv((t + 1) * KTILE, buf ^ 1);
        CP_COMMIT();

        // ---- S = Q @ K^T : warp computes 16 x 128, k = 64 ----
        float acc_s[16][4];
#pragma unroll
        for (int i = 0; i < 16; i++)
#pragma unroll
            for (int tt = 0; tt < 4; tt++) acc_s[i][tt] = 0.f;

#pragma unroll
        for (int kk4 = 0; kk4 < 4; kk4++) {
            uint32_t bk[8][4];
#pragma unroll
            for (int ntp = 0; ntp < 8; ntp++)
                ldsm_x4(bk[ntp], swz(kbuf[buf],
                    (ntp * 16 + ((lane >> 4) << 3) + (lane & 7)) * 128
                    + (kk4 * 16 + (((lane >> 3) & 1) << 3)) * 2));
#pragma unroll
            for (int nt = 0; nt < 16; nt++)
                mma_f16(acc_s[nt], aq[kk4], &bk[nt >> 1][(nt & 1) * 2]);
        }

        // ---- g(s) = (s+1)^2 + 1 in place; accumulate denom ----
#pragma unroll
        for (int nt = 0; nt < 16; nt++) {
            float u;
            u = acc_s[nt][0] + 1.f; acc_s[nt][0] = fmaf(u, u, 1.f);
            u = acc_s[nt][1] + 1.f; acc_s[nt][1] = fmaf(u, u, 1.f);
            u = acc_s[nt][2] + 1.f; acc_s[nt][2] = fmaf(u, u, 1.f);
            u = acc_s[nt][3] + 1.f; acc_s[nt][3] = fmaf(u, u, 1.f);
            if (nt & 1) {
                dn0b += acc_s[nt][0] + acc_s[nt][1];
                dn1b += acc_s[nt][2] + acc_s[nt][3];
            } else {
                dn0a += acc_s[nt][0] + acc_s[nt][1];
                dn1a += acc_s[nt][2] + acc_s[nt][3];
            }
        }

        // ---- O += P @ V : P via register repack (C-frag -> A-frag) ----
#pragma unroll
        for (int kc = 0; kc < 8; kc++) {
            uint32_t ap[4];
            ap[0] = packh2(acc_s[2 * kc    ][0], acc_s[2 * kc    ][1]);
            ap[1] = packh2(acc_s[2 * kc    ][2], acc_s[2 * kc    ][3]);
            ap[2] = packh2(acc_s[2 * kc + 1][0], acc_s[2 * kc + 1][1]);
            ap[3] = packh2(acc_s[2 * kc + 1][2], acc_s[2 * kc + 1][3]);
            uint32_t bv[4][4];
#pragma unroll
            for (int dp = 0; dp < 4; dp++)
                ldsm_x4_trans(bv[dp], swz(vbuf[buf],
                    (kc * 16 + (((lane >> 3) & 1) << 3) + (lane & 7)) * 128
                    + (dp * 16 + ((lane >> 4) << 3)) * 2));
#pragma unroll
            for (int nt = 0; nt < 8; nt++)
                mma_f16(acc_o[nt], ap, &bv[nt >> 1][(nt & 1) * 2]);
        }
    }

    // ---- finalize denom (full row within this warp) ----
    float dn0 = dn0a + dn0b;
    float dn1 = dn1a + dn1b;
    dn0 += __shfl_xor_sync(0xffffffffu, dn0, 1);
    dn0 += __shfl_xor_sync(0xffffffffu, dn0, 2);
    dn1 += __shfl_xor_sync(0xffffffffu, dn1, 1);
    dn1 += __shfl_xor_sync(0xffffffffu, dn1, 2);
    const float inv1 = 1.f / dn0;
    const float inv2 = 1.f / dn1;

    // ---- store fp16 ----
    const int r1 = pm0 + grp, r2 = r1 + 8;
#pragma unroll
    for (int nt = 0; nt < 8; nt++) {
        const int c = h * D_HEAD + nt * 8 + 2 * qd;
        const size_t base1 = (size_t)(b * N_TOK + row0 + r1) * C_DIM + c;
        const size_t base2 = (size_t)(b * N_TOK + row0 + r2) * C_DIM + c;
        *(__half2*)&out[base1] = __floats2half2_rn(acc_o[nt][0] * inv1, acc_o[nt][1] * inv1);
        *(__half2*)&out[base2] = __floats2half2_rn(acc_o[nt][2] * inv2, acc_o[nt][3] * inv2);
    }
}

// ============================================================
// launcher
// ============================================================
extern "C" void kernel_launch(void* const* d_in, const int* in_sizes, int n_in,
                              void* d_out, int out_size)
{
    const float* x      = (const float*)d_in[0];
    const float* w_qkv  = (const float*)d_in[1];
    const float* w_proj = (const float*)d_in[2];
    const float* b_proj = (const float*)d_in[3];
    float* out = (float*)d_out;

    __half *qkv_s, *attn_s, *xh_s, *wqkvT_s, *wprojT_s;
    cudaGetSymbolAddress((void**)&qkv_s,    g_qkv);
    cudaGetSymbolAddress((void**)&attn_s,   g_attn);
    cudaGetSymbolAddress((void**)&xh_s,     g_xh);
    cudaGetSymbolAddress((void**)&wqkvT_s,  g_wqkvT);
    cudaGetSymbolAddress((void**)&wprojT_s, g_wprojT);

    cudaFuncSetAttribute(gemm1_f16, cudaFuncAttributeMaxDynamicSharedMemorySize,
                         (int)G1_SMEM_BYTES);
    cudaFuncSetAttribute(gemm2_f16, cudaFuncAttributeMaxDynamicSharedMemorySize,
                         (int)G2_SMEM_BYTES);
    cudaFuncSetAttribute(attn_f16, cudaFuncAttributeMaxDynamicSharedMemorySize,
                         (int)ATTN_SMEM_BYTES);

    const int M = B_SZ * N_TOK;  // 8192

    // ---- fused pre-pass (single launch) ----
    prepass_kernel<<<PP_XBLKS + PP_WQBLKS + PP_WPBLKS, 256>>>(
        x, xh_s, w_qkv, wqkvT_s, w_proj, wprojT_s);

    // 1) qkv = x @ w_qkv  (fp16 out, Q cols pre-scaled) — 256x128 tiles
    gemm1_f16<<<dim3(3 * C_DIM / 128, M / 256), 256, G1_SMEM_BYTES>>>(
        xh_s, wqkvT_s, qkv_s, M, 3 * C_DIM, C_DIM);

    // 2) fused Taylor attention -> fp16
    attn_f16<<<dim3(N_TOK / QROWS, B_SZ * H_NUM), 128, ATTN_SMEM_BYTES>>>(qkv_s, attn_s);

    // 3) out = attn @ w_proj + b_proj  (fp32 out) — 256thr/64x32-warp
    gemm2_f16<<<dim3(C_DIM / 128, M / 128), 256, G2_SMEM_BYTES>>>(
        attn_s, wprojT_s, b_proj, out, M, C_DIM, C_DIM);
}

// round 16
// speedup vs baseline: 1.0933x; 1.0933x over previous
#include <cuda_runtime.h>
#include <cuda_fp16.h>
#include <cstdint>
#include <cstddef>

// ---------------- problem constants ----------------
#define B_SZ   8
#define N_TOK  1024
#define C_DIM  768
#define H_NUM  12
#define D_HEAD 64
#define SCALE_Q 0.125f   // 64^-0.5

// ---------------- scratch (device globals; no cudaMalloc allowed) ----------------
__device__ __half g_qkv [(size_t)B_SZ * N_TOK * 3 * C_DIM];   // fp16, Q pre-scaled
__device__ __half g_attn[(size_t)B_SZ * N_TOK * C_DIM];       // fp16 attention out
__device__ __half g_xh  [(size_t)B_SZ * N_TOK * C_DIM];       // x -> fp16
__device__ __half g_wqkvT[(size_t)3 * C_DIM * C_DIM];         // w_qkv^T [2304][768] fp16
__device__ __half g_wprojT[(size_t)C_DIM * C_DIM];            // w_proj^T [768][768] fp16

// ---------------- helpers ----------------
__device__ __forceinline__ void mma_f16(float* d, const uint32_t* a, const uint32_t* b) {
    asm volatile(
        "mma.sync.aligned.m16n8k16.row.col.f32.f16.f16.f32 "
        "{%0,%1,%2,%3}, {%4,%5,%6,%7}, {%8,%9}, {%0,%1,%2,%3};"
        : "+f"(d[0]), "+f"(d[1]), "+f"(d[2]), "+f"(d[3])
        : "r"(a[0]), "r"(a[1]), "r"(a[2]), "r"(a[3]),
          "r"(b[0]), "r"(b[1]));
}

__device__ __forceinline__ void ldsm_x4(uint32_t* r, const void* p) {
    uint32_t addr = (uint32_t)__cvta_generic_to_shared(p);
    asm volatile(
        "ldmatrix.sync.aligned.m8n8.x4.shared.b16 {%0,%1,%2,%3}, [%4];"
        : "=r"(r[0]), "=r"(r[1]), "=r"(r[2]), "=r"(r[3]) : "r"(addr));
}

__device__ __forceinline__ void ldsm_x4_trans(uint32_t* r, const void* p) {
    uint32_t addr = (uint32_t)__cvta_generic_to_shared(p);
    asm volatile(
        "ldmatrix.sync.aligned.m8n8.x4.trans.shared.b16 {%0,%1,%2,%3}, [%4];"
        : "=r"(r[0]), "=r"(r[1]), "=r"(r[2]), "=r"(r[3]) : "r"(addr));
}

__device__ __forceinline__ void cp_async16(void* smem_dst, const void* gmem_src) {
    uint32_t a = (uint32_t)__cvta_generic_to_shared(smem_dst);
    asm volatile("cp.async.cg.shared.global [%0], [%1], 16;" :: "r"(a), "l"(gmem_src));
}
#define CP_COMMIT()  asm volatile("cp.async.commit_group;")
#define CP_WAIT(n)   asm volatile("cp.async.wait_group %0;" :: "n"(n))

__device__ __forceinline__ uint32_t packh2(float a, float b) {
    __half2 h = __floats2half2_rn(a, b);
    return *(uint32_t*)&h;
}

// SW128 swizzle on byte offsets (rows of 128B)
__device__ __forceinline__ char* swz(char* base, int byteoff) {
    return base + (byteoff ^ ((byteoff >> 3) & 0x70));
}

// ============================================================
// fused pre-pass: x->fp16 (4 float4/thread) | transpose weights
// ============================================================
#define PP_XBLKS  (B_SZ * N_TOK * C_DIM / 4 / 1024)                 // 1536
#define PP_WQBLKS ((3 * C_DIM / 32) * (C_DIM / 32))                 // 1728
#define PP_WPBLKS ((C_DIM / 32) * (C_DIM / 32))                     // 576

__global__ __launch_bounds__(256) void prepass_kernel(
    const float* __restrict__ x,     __half* __restrict__ xh,
    const float* __restrict__ wqkv,  __half* __restrict__ wqkvT,
    const float* __restrict__ wproj, __half* __restrict__ wprojT)
{
    const int blk = blockIdx.x;
    const int tid = threadIdx.x;
    if (blk < PP_XBLKS) {
        const int i0 = blk * 1024 + tid;
#pragma unroll
        for (int j = 0; j < 4; j++) {
            const int i = i0 + j * 256;
            float4 v = ((const float4*)x)[i];
            __half2* o = (__half2*)(xh + (size_t)i * 4);
            o[0] = __floats2half2_rn(v.x, v.y);
            o[1] = __floats2half2_rn(v.z, v.w);
        }
        return;
    }
    __shared__ float tile[32][33];
    const float* in;
    __half* outp;
    int R, Ncols, bi;
    if (blk < PP_XBLKS + PP_WQBLKS) {
        bi = blk - PP_XBLKS; in = wqkv; outp = wqkvT; R = C_DIM; Ncols = 3 * C_DIM;
    } else {
        bi = blk - PP_XBLKS - PP_WQBLKS; in = wproj; outp = wprojT; R = C_DIM; Ncols = C_DIM;
    }
    const int nbx = Ncols / 32;
    const int bx = (bi % nbx) * 32, by = (bi / nbx) * 32;
    const int tx = tid & 31, ty = tid >> 5;
#pragma unroll
    for (int j = 0; j < 32; j += 8)
        tile[ty + j][tx] = in[(size_t)(by + ty + j) * Ncols + bx + tx];
    __syncthreads();
#pragma unroll
    for (int j = 0; j < 32; j += 8)
        outp[(size_t)(bx + ty + j) * R + by + tx] = __float2half_rn(tile[tx][ty + j]);
}

// ============================================================
// GEMM1: 128x128x32 CTA tile, 128 threads / 4 warps,
// warp tile 64x64, 5-stage cp.async, 2 CTAs/SM.
// fp16 out, cols < C_DIM scaled by SCALE_Q.
// ============================================================
#define GPITCH 40
#define G1STAGES 5
#define G1_SMEM_BYTES (G1STAGES * 2 * 128 * GPITCH * 2)   // 102400

__global__ __launch_bounds__(128, 2) void gemm1_f16(
    const __half* __restrict__ A, const __half* __restrict__ BT,
    __half* __restrict__ Cout, int M, int N, int K)
{
    extern __shared__ __half smh[];
    __half (*As)[128][GPITCH] = (__half(*)[128][GPITCH])(smh);
    __half (*Bs)[128][GPITCH] = (__half(*)[128][GPITCH])(smh + G1STAGES * 128 * GPITCH);

    const int tid  = threadIdx.x;
    const int wid  = tid >> 5;
    const int lane = tid & 31;
    const int grp  = lane >> 2;
    const int qd   = lane & 3;

    const int brow = blockIdx.y * 128;
    const int bcol = blockIdx.x * 128;
    const int m_base = (wid & 1) * 64;
    const int n_base = (wid >> 1) * 64;

    float acc[4][8][4];
#pragma unroll
    for (int i = 0; i < 4; i++)
#pragma unroll
        for (int j = 0; j < 8; j++)
#pragma unroll
            for (int t = 0; t < 4; t++) acc[i][j][t] = 0.f;

    auto load_tile = [&](int t, int s) {
        const int k0 = t * 32;
#pragma unroll
        for (int i = 0; i < 4; i++) {
            const int ch = tid + i * 128;
            const int r = ch >> 2, co = (ch & 3) * 8;
            cp_async16(&As[s][r][co], &A [(size_t)(brow + r) * K + k0 + co]);
            cp_async16(&Bs[s][r][co], &BT[(size_t)(bcol + r) * K + k0 + co]);
        }
    };

    const int T = K / 32;
#pragma unroll
    for (int t = 0; t < G1STAGES - 1; t++) {
        if (t < T) load_tile(t, t);
        CP_COMMIT();
    }

    int buf = 0, lbuf = G1STAGES - 1;
    for (int t = 0; t < T; t++) {
        CP_WAIT(G1STAGES - 2);
        __syncthreads();
        if (t + G1STAGES - 1 < T) load_tile(t + G1STAGES - 1, lbuf);
        CP_COMMIT();

#pragma unroll
        for (int ks = 0; ks < 32; ks += 16) {
            uint32_t af[4][4];
#pragma unroll
            for (int mt = 0; mt < 4; mt++)
                ldsm_x4(af[mt], &As[buf][m_base + mt * 16 + (lane & 15)][ks + ((lane >> 4) << 3)]);
            uint32_t bf[4][4];
#pragma unroll
            for (int ntp = 0; ntp < 4; ntp++)
                ldsm_x4(bf[ntp], &Bs[buf][n_base + ntp * 16 + ((lane >> 4) << 3) + (lane & 7)]
                                         [ks + (((lane >> 3) & 1) << 3)]);
#pragma unroll
            for (int nt = 0; nt < 8; nt++) {
                const uint32_t* bb = &bf[nt >> 1][(nt & 1) * 2];
#pragma unroll
                for (int mt = 0; mt < 4; mt++)
                    mma_f16(acc[mt][nt], af[mt], bb);
            }
        }
        if (++buf == G1STAGES) buf = 0;
        if (++lbuf == G1STAGES) lbuf = 0;
    }

#pragma unroll
    for (int mt = 0; mt < 4; mt++) {
        const int r1 = brow + m_base + mt * 16 + grp;
        const int r2 = r1 + 8;
#pragma unroll
        for (int nt = 0; nt < 8; nt++) {
            const int c = bcol + n_base + nt * 8 + 2 * qd;
            const float s = (c < C_DIM) ? SCALE_Q : 1.f;
            *(__half2*)&Cout[(size_t)r1 * N + c] =
                __floats2half2_rn(acc[mt][nt][0] * s, acc[mt][nt][1] * s);
            *(__half2*)&Cout[(size_t)r2 * N + c] =
                __floats2half2_rn(acc[mt][nt][2] * s, acc[mt][nt][3] * s);
        }
    }
}

// ============================================================
// GEMM2: 128x128x32 tile, 256 threads / 8 warps, warp 64x32,
// 5-stage cp.async, 2 CTAs/SM. fp32 out + bias. (measured best)
// ============================================================
#define G2STAGES 5
#define G2_SMEM_BYTES (G2STAGES * 2 * 128 * GPITCH * 2)   // 102400

__global__ __launch_bounds__(256, 2) void gemm2_f16(
    const __half* __restrict__ A, const __half* __restrict__ BT,
    const float* __restrict__ bias, float* __restrict__ C,
    int M, int N, int K)
{
    extern __shared__ __half smh[];
    __half (*As)[128][GPITCH] = (__half(*)[128][GPITCH])(smh);
    __half (*Bs)[128][GPITCH] = (__half(*)[128][GPITCH])(smh + G2STAGES * 128 * GPITCH);

    const int tid  = threadIdx.x;
    const int wid  = tid >> 5;
    const int lane = tid & 31;
    const int grp  = lane >> 2;
    const int qd   = lane & 3;

    const int brow = blockIdx.y * 128;
    const int bcol = blockIdx.x * 128;
    const int m_base = (wid & 1) * 64;
    const int n_base = (wid >> 1) * 32;

    float acc[4][4][4];
#pragma unroll
    for (int i = 0; i < 4; i++)
#pragma unroll
        for (int j = 0; j < 4; j++)
#pragma unroll
            for (int t = 0; t < 4; t++) acc[i][j][t] = 0.f;

    auto load_tile = [&](int t, int s) {
        const int k0 = t * 32;
#pragma unroll
        for (int i = 0; i < 2; i++) {
            const int ch = tid + i * 256;
            const int r = ch >> 2, co = (ch & 3) * 8;
            cp_async16(&As[s][r][co], &A [(size_t)(brow + r) * K + k0 + co]);
            cp_async16(&Bs[s][r][co], &BT[(size_t)(bcol + r) * K + k0 + co]);
        }
    };

    const int T = K / 32;
#pragma unroll
    for (int t = 0; t < G2STAGES - 1; t++) {
        if (t < T) load_tile(t, t);
        CP_COMMIT();
    }

    int buf = 0, lbuf = (G2STAGES - 1) % G2STAGES;
    for (int t = 0; t < T; t++) {
        CP_WAIT(G2STAGES - 2);
        __syncthreads();
        if (t + G2STAGES - 1 < T) load_tile(t + G2STAGES - 1, lbuf);
        CP_COMMIT();

#pragma unroll
        for (int ks = 0; ks < 32; ks += 16) {
            uint32_t af[4][4];
#pragma unroll
            for (int mt = 0; mt < 4; mt++)
                ldsm_x4(af[mt], &As[buf][m_base + mt * 16 + (lane & 15)][ks + ((lane >> 4) << 3)]);
            uint32_t bf[2][4];
#pragma unroll
            for (int ntp = 0; ntp < 2; ntp++)
                ldsm_x4(bf[ntp], &Bs[buf][n_base + ntp * 16 + ((lane >> 4) << 3) + (lane & 7)]
                                         [ks + (((lane >> 3) & 1) << 3)]);
#pragma unroll
            for (int nt = 0; nt < 4; nt++) {
                const uint32_t* bb = &bf[nt >> 1][(nt & 1) * 2];
#pragma unroll
                for (int mt = 0; mt < 4; mt++)
                    mma_f16(acc[mt][nt], af[mt], bb);
            }
        }
        if (++buf == G2STAGES) buf = 0;
        if (++lbuf == G2STAGES) lbuf = 0;
    }

#pragma unroll
    for (int mt = 0; mt < 4; mt++) {
        const int r1 = brow + m_base + mt * 16 + grp;
        const int r2 = r1 + 8;
#pragma unroll
        for (int nt = 0; nt < 4; nt++) {
            const int c = bcol + n_base + nt * 8 + 2 * qd;
            const float b0 = __ldg(&bias[c]), b1 = __ldg(&bias[c + 1]);
            *(float2*)&C[(size_t)r1 * N + c] =
                make_float2(acc[mt][nt][0] + b0, acc[mt][nt][1] + b1);
            *(float2*)&C[(size_t)r2 * N + c] =
                make_float2(acc[mt][nt][2] + b0, acc[mt][nt][3] + b1);
        }
    }
}

// ============================================================
// Fused Taylor attention — R9 config (measured best):
// 128 threads (4 warps), Q tile 64, KV tile 128 double-buffered,
// SW128 smem, Q aliased onto KV buf1, 3 CTAs/SM, register repack.
// g(s) = (s+1)^2 + 1 (= 2*f; scale cancels in normalization).
// ============================================================
#define QROWS 64
#define KTILE 128
#define TILE_B 16384
#define ATTN_SMEM_BYTES (4 * TILE_B)

__global__ __launch_bounds__(128, 3) void attn_f16(
    const __half* __restrict__ qkv, __half* __restrict__ out)
{
    extern __shared__ char smc[];
    char* const kbuf[2] = { smc,          smc + 2 * TILE_B };
    char* const vbuf[2] = { smc + TILE_B, smc + 3 * TILE_B };
    char* const qbuf    = smc + 2 * TILE_B;   // alias: K1 region

    const int tid  = threadIdx.x;
    const int wid  = tid >> 5;
    const int lane = tid & 31;
    const int grp  = lane >> 2;
    const int qd   = lane & 3;

    const int b    = blockIdx.y / H_NUM;
    const int h    = blockIdx.y % H_NUM;
    const int row0 = blockIdx.x * QROWS;

    const int pm0 = wid * 16;   // warp's 16 Q-rows

    auto load_kv = [&](int m0, int s) {
#pragma unroll
        for (int l = 0; l < 8; l++) {
            const int ch = tid + l * 128;
            const int r = ch >> 3, cb = (ch & 7) * 16;
            const size_t nb = (size_t)(b * N_TOK + m0 + r) * 3;
            cp_async16(swz(kbuf[s], r * 128 + cb), &qkv[(nb + 1) * C_DIM + h * D_HEAD + cb / 2]);
            cp_async16(swz(vbuf[s], r * 128 + cb), &qkv[(nb + 2) * C_DIM + h * D_HEAD + cb / 2]);
        }
    };

    // prologue: Q (into qbuf = K1) + KV(0)
#pragma unroll
    for (int l = 0; l < 4; l++) {
        const int ch = tid + l * 128;
        const int r = ch >> 3, cb = (ch & 7) * 16;
        cp_async16(swz(qbuf, r * 128 + cb),
                   &qkv[((size_t)(b * N_TOK + row0 + r) * 3) * C_DIM + h * D_HEAD + cb / 2]);
    }
    load_kv(0, 0);
    CP_COMMIT();
    CP_WAIT(0);
    __syncthreads();

    // hoist Q fragments, then free qbuf for KV buf1
    uint32_t aq[4][4];
#pragma unroll
    for (int kk4 = 0; kk4 < 4; kk4++)
        ldsm_x4(aq[kk4], swz(qbuf, (pm0 + (lane & 15)) * 128
                                   + (kk4 * 16 + ((lane >> 4) << 3)) * 2));
    __syncthreads();   // all warps hold aq before buf1 is overwritten

    float acc_o[8][4];
#pragma unroll
    for (int i = 0; i < 8; i++)
#pragma unroll
        for (int t = 0; t < 4; t++) acc_o[i][t] = 0.f;
    float dn0a = 0.f, dn0b = 0.f, dn1a = 0.f, dn1b = 0.f;

    const int NT = N_TOK / KTILE;   // 8
    for (int t = 0; t < NT; t++) {
        const int buf = t & 1;
        if (t > 0) {
            CP_WAIT(0);
            __syncthreads();
        }
        if (t + 1 < NT) load_kv((t + 1) * KTILE, buf ^ 1);
        CP_COMMIT();

        // ---- S = Q @ K^T : warp computes 16 x 128, k = 64 ----
        float acc_s[16][4];
#pragma unroll
        for (int i = 0; i < 16; i++)
#pragma unroll
            for (int tt = 0; tt < 4; tt++) acc_s[i][tt] = 0.f;

#pragma unroll
        for (int kk4 = 0; kk4 < 4; kk4++) {
            uint32_t bk[8][4];
#pragma unroll
            for (int ntp = 0; ntp < 8; ntp++)
                ldsm_x4(bk[ntp], swz(kbuf[buf],
                    (ntp * 16 + ((lane >> 4) << 3) + (lane & 7)) * 128
                    + (kk4 * 16 + (((lane >> 3) & 1) << 3)) * 2));
#pragma unroll
            for (int nt = 0; nt < 16; nt++)
                mma_f16(acc_s[nt], aq[kk4], &bk[nt >> 1][(nt & 1) * 2]);
        }

        // ---- g(s) = (s+1)^2 + 1 in place; accumulate denom ----
#pragma unroll
        for (int nt = 0; nt < 16; nt++) {
            float u;
            u = acc_s[nt][0] + 1.f; acc_s[nt][0] = fmaf(u, u, 1.f);
            u = acc_s[nt][1] + 1.f; acc_s[nt][1] = fmaf(u, u, 1.f);
            u = acc_s[nt][2] + 1.f; acc_s[nt][2] = fmaf(u, u, 1.f);
            u = acc_s[nt][3] + 1.f; acc_s[nt][3] = fmaf(u, u, 1.f);
            if (nt & 1) {
                dn0b += acc_s[nt][0] + acc_s[nt][1];
                dn1b += acc_s[nt][2] + acc_s[nt][3];
            } else {
                dn0a += acc_s[nt][0] + acc_s[nt][1];
                dn1a += acc_s[nt][2] + acc_s[nt][3];
            }
        }

        // ---- O += P @ V : P via register repack (C-frag -> A-frag) ----
#pragma unroll
        for (int kc = 0; kc < 8; kc++) {
            uint32_t ap[4];
            ap[0] = packh2(acc_s[2 * kc    ][0], acc_s[2 * kc    ][1]);
            ap[1] = packh2(acc_s[2 * kc    ][2], acc_s[2 * kc    ][3]);
            ap[2] = packh2(acc_s[2 * kc + 1][0], acc_s[2 * kc + 1][1]);
            ap[3] = packh2(acc_s[2 * kc + 1][2], acc_s[2 * kc + 1][3]);
            uint32_t bv[4][4];
#pragma unroll
            for (int dp = 0; dp < 4; dp++)
                ldsm_x4_trans(bv[dp], swz(vbuf[buf],
                    (kc * 16 + (((lane >> 3) & 1) << 3) + (lane & 7)) * 128
                    + (dp * 16 + ((lane >> 4) << 3)) * 2));
#pragma unroll
            for (int nt = 0; nt < 8; nt++)
                mma_f16(acc_o[nt], ap, &bv[nt >> 1][(nt & 1) * 2]);
        }
    }

    // ---- finalize denom (full row within this warp) ----
    float dn0 = dn0a + dn0b;
    float dn1 = dn1a + dn1b;
    dn0 += __shfl_xor_sync(0xffffffffu, dn0, 1);
    dn0 += __shfl_xor_sync(0xffffffffu, dn0, 2);
    dn1 += __shfl_xor_sync(0xffffffffu, dn1, 1);
    dn1 += __shfl_xor_sync(0xffffffffu, dn1, 2);
    const float inv1 = 1.f / dn0;
    const float inv2 = 1.f / dn1;

    // ---- store fp16 ----
    const int r1 = pm0 + grp, r2 = r1 + 8;
#pragma unroll
    for (int nt = 0; nt < 8; nt++) {
        const int c = h * D_HEAD + nt * 8 + 2 * qd;
        const size_t base1 = (size_t)(b * N_TOK + row0 + r1) * C_DIM + c;
        const size_t base2 = (size_t)(b * N_TOK + row0 + r2) * C_DIM + c;
        *(__half2*)&out[base1] = __floats2half2_rn(acc_o[nt][0] * inv1, acc_o[nt][1] * inv1);
        *(__half2*)&out[base2] = __floats2half2_rn(acc_o[nt][2] * inv2, acc_o[nt][3] * inv2);
    }
}

// ============================================================
// launcher
// ============================================================
extern "C" void kernel_launch(void* const* d_in, const int* in_sizes, int n_in,
                              void* d_out, int out_size)
{
    const float* x      = (const float*)d_in[0];
    const float* w_qkv  = (const float*)d_in[1];
    const float* w_proj = (const float*)d_in[2];
    const float* b_proj = (const float*)d_in[3];
    float* out = (float*)d_out;

    __half *qkv_s, *attn_s, *xh_s, *wqkvT_s, *wprojT_s;
    cudaGetSymbolAddress((void**)&qkv_s,    g_qkv);
    cudaGetSymbolAddress((void**)&attn_s,   g_attn);
    cudaGetSymbolAddress((void**)&xh_s,     g_xh);
    cudaGetSymbolAddress((void**)&wqkvT_s,  g_wqkvT);
    cudaGetSymbolAddress((void**)&wprojT_s, g_wprojT);

    cudaFuncSetAttribute(gemm1_f16, cudaFuncAttributeMaxDynamicSharedMemorySize,
                         (int)G1_SMEM_BYTES);
    cudaFuncSetAttribute(gemm2_f16, cudaFuncAttributeMaxDynamicSharedMemorySize,
                         (int)G2_SMEM_BYTES);
    cudaFuncSetAttribute(attn_f16, cudaFuncAttributeMaxDynamicSharedMemorySize,
                         (int)ATTN_SMEM_BYTES);

    const int M = B_SZ * N_TOK;  // 8192

    // ---- fused pre-pass (single launch) ----
    prepass_kernel<<<PP_XBLKS + PP_WQBLKS + PP_WPBLKS, 256>>>(
        x, xh_s, w_qkv, wqkvT_s, w_proj, wprojT_s);

    // 1) qkv = x @ w_qkv  (fp16 out, Q cols pre-scaled) — 128thr/64x64-warp
    gemm1_f16<<<dim3(3 * C_DIM / 128, M / 128), 128, G1_SMEM_BYTES>>>(
        xh_s, wqkvT_s, qkv_s, M, 3 * C_DIM, C_DIM);

    // 2) fused Taylor attention -> fp16
    attn_f16<<<dim3(N_TOK / QROWS, B_SZ * H_NUM), 128, ATTN_SMEM_BYTES>>>(qkv_s, attn_s);

    // 3) out = attn @ w_proj + b_proj  (fp32 out) — 256thr/64x32-warp
    gemm2_f16<<<dim3(C_DIM / 128, M / 128), 256, G2_SMEM_BYTES>>>(
        attn_s, wprojT_s, b_proj, out, M, C_DIM, C_DIM);
}

// round 17
// speedup vs baseline: 1.1094x; 1.0147x over previous
#include <cuda_runtime.h>
#include <cuda_fp16.h>
#include <cstdint>
#include <cstddef>

// ---------------- problem constants ----------------
#define B_SZ   8
#define N_TOK  1024
#define C_DIM  768
#define H_NUM  12
#define D_HEAD 64
#define SCALE_Q 0.125f   // 64^-0.5

// ---------------- scratch (device globals; no cudaMalloc allowed) ----------------
__device__ __half g_qkv [(size_t)B_SZ * N_TOK * 3 * C_DIM];   // fp16, Q pre-scaled
__device__ __half g_attn[(size_t)B_SZ * N_TOK * C_DIM];       // fp16 attention out
__device__ __half g_xh  [(size_t)B_SZ * N_TOK * C_DIM];       // x -> fp16
__device__ __half g_wqkvT[(size_t)3 * C_DIM * C_DIM];         // w_qkv^T [2304][768] fp16
__device__ __half g_wprojT[(size_t)C_DIM * C_DIM];            // w_proj^T [768][768] fp16

// ---------------- helpers ----------------
__device__ __forceinline__ void mma_f16(float* d, const uint32_t* a, const uint32_t* b) {
    asm volatile(
        "mma.sync.aligned.m16n8k16.row.col.f32.f16.f16.f32 "
        "{%0,%1,%2,%3}, {%4,%5,%6,%7}, {%8,%9}, {%0,%1,%2,%3};"
        : "+f"(d[0]), "+f"(d[1]), "+f"(d[2]), "+f"(d[3])
        : "r"(a[0]), "r"(a[1]), "r"(a[2]), "r"(a[3]),
          "r"(b[0]), "r"(b[1]));
}

__device__ __forceinline__ void ldsm_x4(uint32_t* r, const void* p) {
    uint32_t addr = (uint32_t)__cvta_generic_to_shared(p);
    asm volatile(
        "ldmatrix.sync.aligned.m8n8.x4.shared.b16 {%0,%1,%2,%3}, [%4];"
        : "=r"(r[0]), "=r"(r[1]), "=r"(r[2]), "=r"(r[3]) : "r"(addr));
}

__device__ __forceinline__ void ldsm_x4_trans(uint32_t* r, const void* p) {
    uint32_t addr = (uint32_t)__cvta_generic_to_shared(p);
    asm volatile(
        "ldmatrix.sync.aligned.m8n8.x4.trans.shared.b16 {%0,%1,%2,%3}, [%4];"
        : "=r"(r[0]), "=r"(r[1]), "=r"(r[2]), "=r"(r[3]) : "r"(addr));
}

__device__ __forceinline__ void cp_async16(void* smem_dst, const void* gmem_src) {
    uint32_t a = (uint32_t)__cvta_generic_to_shared(smem_dst);
    asm volatile("cp.async.cg.shared.global [%0], [%1], 16;" :: "r"(a), "l"(gmem_src));
}
#define CP_COMMIT()  asm volatile("cp.async.commit_group;")
#define CP_WAIT(n)   asm volatile("cp.async.wait_group %0;" :: "n"(n))

__device__ __forceinline__ uint32_t packh2(float a, float b) {
    __half2 h = __floats2half2_rn(a, b);
    return *(uint32_t*)&h;
}

// SW128 swizzle on byte offsets (rows of 128B)
__device__ __forceinline__ char* swz(char* base, int byteoff) {
    return base + (byteoff ^ ((byteoff >> 3) & 0x70));
}

// ============================================================
// fused pre-pass: x->fp16 (4 float4/thread) | transpose weights
// ============================================================
#define PP_XBLKS  (B_SZ * N_TOK * C_DIM / 4 / 1024)                 // 1536
#define PP_WQBLKS ((3 * C_DIM / 32) * (C_DIM / 32))                 // 1728
#define PP_WPBLKS ((C_DIM / 32) * (C_DIM / 32))                     // 576

__global__ __launch_bounds__(256) void prepass_kernel(
    const float* __restrict__ x,     __half* __restrict__ xh,
    const float* __restrict__ wqkv,  __half* __restrict__ wqkvT,
    const float* __restrict__ wproj, __half* __restrict__ wprojT)
{
    const int blk = blockIdx.x;
    const int tid = threadIdx.x;
    if (blk < PP_XBLKS) {
        const int i0 = blk * 1024 + tid;
#pragma unroll
        for (int j = 0; j < 4; j++) {
            const int i = i0 + j * 256;
            float4 v = ((const float4*)x)[i];
            __half2* o = (__half2*)(xh + (size_t)i * 4);
            o[0] = __floats2half2_rn(v.x, v.y);
            o[1] = __floats2half2_rn(v.z, v.w);
        }
        return;
    }
    __shared__ float tile[32][33];
    const float* in;
    __half* outp;
    int R, Ncols, bi;
    if (blk < PP_XBLKS + PP_WQBLKS) {
        bi = blk - PP_XBLKS; in = wqkv; outp = wqkvT; R = C_DIM; Ncols = 3 * C_DIM;
    } else {
        bi = blk - PP_XBLKS - PP_WQBLKS; in = wproj; outp = wprojT; R = C_DIM; Ncols = C_DIM;
    }
    const int nbx = Ncols / 32;
    const int bx = (bi % nbx) * 32, by = (bi / nbx) * 32;
    const int tx = tid & 31, ty = tid >> 5;
#pragma unroll
    for (int j = 0; j < 32; j += 8)
        tile[ty + j][tx] = in[(size_t)(by + ty + j) * Ncols + bx + tx];
    __syncthreads();
#pragma unroll
    for (int j = 0; j < 32; j += 8)
        outp[(size_t)(bx + ty + j) * R + by + tx] = __float2half_rn(tile[tx][ty + j]);
}

// ============================================================
// GEMM1: 128x128x64 CTA tile, 128 threads / 4 warps,
// warp tile 64x64, 3-stage cp.async (2-tile prefetch), 2 CTAs/SM.
// BK=64: half the barriers, 2x MMA run per sync window.
// fp16 out, cols < C_DIM scaled by SCALE_Q.
// ============================================================
#define G1PITCH 72   // 64 + 8 halves -> 144B row pitch (9 mod 8 = 1: conflict-free)
#define G1STAGES 3
#define G1_SMEM_BYTES (G1STAGES * 2 * 128 * G1PITCH * 2)   // 110592

__global__ __launch_bounds__(128, 2) void gemm1_f16(
    const __half* __restrict__ A, const __half* __restrict__ BT,
    __half* __restrict__ Cout, int M, int N, int K)
{
    extern __shared__ __half smh[];
    __half (*As)[128][G1PITCH] = (__half(*)[128][G1PITCH])(smh);
    __half (*Bs)[128][G1PITCH] = (__half(*)[128][G1PITCH])(smh + G1STAGES * 128 * G1PITCH);

    const int tid  = threadIdx.x;
    const int wid  = tid >> 5;
    const int lane = tid & 31;
    const int grp  = lane >> 2;
    const int qd   = lane & 3;

    const int brow = blockIdx.y * 128;
    const int bcol = blockIdx.x * 128;
    const int m_base = (wid & 1) * 64;
    const int n_base = (wid >> 1) * 64;

    float acc[4][8][4];
#pragma unroll
    for (int i = 0; i < 4; i++)
#pragma unroll
        for (int j = 0; j < 8; j++)
#pragma unroll
            for (int t = 0; t < 4; t++) acc[i][j][t] = 0.f;

    // per stage: A = 128 rows x 64 cols x 2B = 16KB = 1024 chunks -> 8/thread (ditto B)
    auto load_tile = [&](int t, int s) {
        const int k0 = t * 64;
#pragma unroll
        for (int i = 0; i < 8; i++) {
            const int ch = tid + i * 128;
            const int r = ch >> 3, co = (ch & 7) * 8;
            cp_async16(&As[s][r][co], &A [(size_t)(brow + r) * K + k0 + co]);
            cp_async16(&Bs[s][r][co], &BT[(size_t)(bcol + r) * K + k0 + co]);
        }
    };

    const int T = K / 64;   // 12
#pragma unroll
    for (int t = 0; t < G1STAGES - 1; t++) {
        if (t < T) load_tile(t, t);
        CP_COMMIT();
    }

    int buf = 0, lbuf = G1STAGES - 1;
    for (int t = 0; t < T; t++) {
        CP_WAIT(G1STAGES - 2);
        __syncthreads();
        if (t + G1STAGES - 1 < T) load_tile(t + G1STAGES - 1, lbuf);
        CP_COMMIT();

#pragma unroll
        for (int ks = 0; ks < 64; ks += 16) {
            uint32_t af[4][4];
#pragma unroll
            for (int mt = 0; mt < 4; mt++)
                ldsm_x4(af[mt], &As[buf][m_base + mt * 16 + (lane & 15)][ks + ((lane >> 4) << 3)]);
            uint32_t bf[4][4];
#pragma unroll
            for (int ntp = 0; ntp < 4; ntp++)
                ldsm_x4(bf[ntp], &Bs[buf][n_base + ntp * 16 + ((lane >> 4) << 3) + (lane & 7)]
                                         [ks + (((lane >> 3) & 1) << 3)]);
#pragma unroll
            for (int nt = 0; nt < 8; nt++) {
                const uint32_t* bb = &bf[nt >> 1][(nt & 1) * 2];
#pragma unroll
                for (int mt = 0; mt < 4; mt++)
                    mma_f16(acc[mt][nt], af[mt], bb);
            }
        }
        if (++buf == G1STAGES) buf = 0;
        if (++lbuf == G1STAGES) lbuf = 0;
    }

#pragma unroll
    for (int mt = 0; mt < 4; mt++) {
        const int r1 = brow + m_base + mt * 16 + grp;
        const int r2 = r1 + 8;
#pragma unroll
        for (int nt = 0; nt < 8; nt++) {
            const int c = bcol + n_base + nt * 8 + 2 * qd;
            const float s = (c < C_DIM) ? SCALE_Q : 1.f;
            *(__half2*)&Cout[(size_t)r1 * N + c] =
                __floats2half2_rn(acc[mt][nt][0] * s, acc[mt][nt][1] * s);
            *(__half2*)&Cout[(size_t)r2 * N + c] =
                __floats2half2_rn(acc[mt][nt][2] * s, acc[mt][nt][3] * s);
        }
    }
}

// ============================================================
// GEMM2: 128x128x32 tile, 256 threads / 8 warps, warp 64x32,
// 5-stage cp.async, 2 CTAs/SM. fp32 out + bias. (measured best)
// ============================================================
#define GPITCH 40
#define G2STAGES 5
#define G2_SMEM_BYTES (G2STAGES * 2 * 128 * GPITCH * 2)   // 102400

__global__ __launch_bounds__(256, 2) void gemm2_f16(
    const __half* __restrict__ A, const __half* __restrict__ BT,
    const float* __restrict__ bias, float* __restrict__ C,
    int M, int N, int K)
{
    extern __shared__ __half smh[];
    __half (*As)[128][GPITCH] = (__half(*)[128][GPITCH])(smh);
    __half (*Bs)[128][GPITCH] = (__half(*)[128][GPITCH])(smh + G2STAGES * 128 * GPITCH);

    const int tid  = threadIdx.x;
    const int wid  = tid >> 5;
    const int lane = tid & 31;
    const int grp  = lane >> 2;
    const int qd   = lane & 3;

    const int brow = blockIdx.y * 128;
    const int bcol = blockIdx.x * 128;
    const int m_base = (wid & 1) * 64;
    const int n_base = (wid >> 1) * 32;

    float acc[4][4][4];
#pragma unroll
    for (int i = 0; i < 4; i++)
#pragma unroll
        for (int j = 0; j < 4; j++)
#pragma unroll
            for (int t = 0; t < 4; t++) acc[i][j][t] = 0.f;

    auto load_tile = [&](int t, int s) {
        const int k0 = t * 32;
#pragma unroll
        for (int i = 0; i < 2; i++) {
            const int ch = tid + i * 256;
            const int r = ch >> 2, co = (ch & 3) * 8;
            cp_async16(&As[s][r][co], &A [(size_t)(brow + r) * K + k0 + co]);
            cp_async16(&Bs[s][r][co], &BT[(size_t)(bcol + r) * K + k0 + co]);
        }
    };

    const int T = K / 32;
#pragma unroll
    for (int t = 0; t < G2STAGES - 1; t++) {
        if (t < T) load_tile(t, t);
        CP_COMMIT();
    }

    int buf = 0, lbuf = (G2STAGES - 1) % G2STAGES;
    for (int t = 0; t < T; t++) {
        CP_WAIT(G2STAGES - 2);
        __syncthreads();
        if (t + G2STAGES - 1 < T) load_tile(t + G2STAGES - 1, lbuf);
        CP_COMMIT();

#pragma unroll
        for (int ks = 0; ks < 32; ks += 16) {
            uint32_t af[4][4];
#pragma unroll
            for (int mt = 0; mt < 4; mt++)
                ldsm_x4(af[mt], &As[buf][m_base + mt * 16 + (lane & 15)][ks + ((lane >> 4) << 3)]);
            uint32_t bf[2][4];
#pragma unroll
            for (int ntp = 0; ntp < 2; ntp++)
                ldsm_x4(bf[ntp], &Bs[buf][n_base + ntp * 16 + ((lane >> 4) << 3) + (lane & 7)]
                                         [ks + (((lane >> 3) & 1) << 3)]);
#pragma unroll
            for (int nt = 0; nt < 4; nt++) {
                const uint32_t* bb = &bf[nt >> 1][(nt & 1) * 2];
#pragma unroll
                for (int mt = 0; mt < 4; mt++)
                    mma_f16(acc[mt][nt], af[mt], bb);
            }
        }
        if (++buf == G2STAGES) buf = 0;
        if (++lbuf == G2STAGES) lbuf = 0;
    }

#pragma unroll
    for (int mt = 0; mt < 4; mt++) {
        const int r1 = brow + m_base + mt * 16 + grp;
        const int r2 = r1 + 8;
#pragma unroll
        for (int nt = 0; nt < 4; nt++) {
            const int c = bcol + n_base + nt * 8 + 2 * qd;
            const float b0 = __ldg(&bias[c]), b1 = __ldg(&bias[c + 1]);
            *(float2*)&C[(size_t)r1 * N + c] =
                make_float2(acc[mt][nt][0] + b0, acc[mt][nt][1] + b1);
            *(float2*)&C[(size_t)r2 * N + c] =
                make_float2(acc[mt][nt][2] + b0, acc[mt][nt][3] + b1);
        }
    }
}

// ============================================================
// Fused Taylor attention — R9 config (measured best):
// 128 threads (4 warps), Q tile 64, KV tile 128 double-buffered,
// SW128 smem, Q aliased onto KV buf1, 3 CTAs/SM, register repack.
// g(s) = (s+1)^2 + 1 (= 2*f; scale cancels in normalization).
// ============================================================
#define QROWS 64
#define KTILE 128
#define TILE_B 16384
#define ATTN_SMEM_BYTES (4 * TILE_B)

__global__ __launch_bounds__(128, 3) void attn_f16(
    const __half* __restrict__ qkv, __half* __restrict__ out)
{
    extern __shared__ char smc[];
    char* const kbuf[2] = { smc,          smc + 2 * TILE_B };
    char* const vbuf[2] = { smc + TILE_B, smc + 3 * TILE_B };
    char* const qbuf    = smc + 2 * TILE_B;   // alias: K1 region

    const int tid  = threadIdx.x;
    const int wid  = tid >> 5;
    const int lane = tid & 31;
    const int grp  = lane >> 2;
    const int qd   = lane & 3;

    const int b    = blockIdx.y / H_NUM;
    const int h    = blockIdx.y % H_NUM;
    const int row0 = blockIdx.x * QROWS;

    const int pm0 = wid * 16;   // warp's 16 Q-rows

    auto load_kv = [&](int m0, int s) {
#pragma unroll
        for (int l = 0; l < 8; l++) {
            const int ch = tid + l * 128;
            const int r = ch >> 3, cb = (ch & 7) * 16;
            const size_t nb = (size_t)(b * N_TOK + m0 + r) * 3;
            cp_async16(swz(kbuf[s], r * 128 + cb), &qkv[(nb + 1) * C_DIM + h * D_HEAD + cb / 2]);
            cp_async16(swz(vbuf[s], r * 128 + cb), &qkv[(nb + 2) * C_DIM + h * D_HEAD + cb / 2]);
        }
    };

    // prologue: Q (into qbuf = K1) + KV(0)
#pragma unroll
    for (int l = 0; l < 4; l++) {
        const int ch = tid + l * 128;
        const int r = ch >> 3, cb = (ch & 7) * 16;
        cp_async16(swz(qbuf, r * 128 + cb),
                   &qkv[((size_t)(b * N_TOK + row0 + r) * 3) * C_DIM + h * D_HEAD + cb / 2]);
    }
    load_kv(0, 0);
    CP_COMMIT();
    CP_WAIT(0);
    __syncthreads();

    // hoist Q fragments, then free qbuf for KV buf1
    uint32_t aq[4][4];
#pragma unroll
    for (int kk4 = 0; kk4 < 4; kk4++)
        ldsm_x4(aq[kk4], swz(qbuf, (pm0 + (lane & 15)) * 128
                                   + (kk4 * 16 + ((lane >> 4) << 3)) * 2));
    __syncthreads();   // all warps hold aq before buf1 is overwritten

    float acc_o[8][4];
#pragma unroll
    for (int i = 0; i < 8; i++)
#pragma unroll
        for (int t = 0; t < 4; t++) acc_o[i][t] = 0.f;
    float dn0a = 0.f, dn0b = 0.f, dn1a = 0.f, dn1b = 0.f;

    const int NT = N_TOK / KTILE;   // 8
    for (int t = 0; t < NT; t++) {
        const int buf = t & 1;
        if (t > 0) {
            CP_WAIT(0);
            __syncthreads();
        }
        if (t + 1 < NT) load_kv((t + 1) * KTILE, buf ^ 1);
        CP_COMMIT();

        // ---- S = Q @ K^T : warp computes 16 x 128, k = 64 ----
        float acc_s[16][4];
#pragma unroll
        for (int i = 0; i < 16; i++)
#pragma unroll
            for (int tt = 0; tt < 4; tt++) acc_s[i][tt] = 0.f;

#pragma unroll
        for (int kk4 = 0; kk4 < 4; kk4++) {
            uint32_t bk[8][4];
#pragma unroll
            for (int ntp = 0; ntp < 8; ntp++)
                ldsm_x4(bk[ntp], swz(kbuf[buf],
                    (ntp * 16 + ((lane >> 4) << 3) + (lane & 7)) * 128
                    + (kk4 * 16 + (((lane >> 3) & 1) << 3)) * 2));
#pragma unroll
            for (int nt = 0; nt < 16; nt++)
                mma_f16(acc_s[nt], aq[kk4], &bk[nt >> 1][(nt & 1) * 2]);
        }

        // ---- g(s) = (s+1)^2 + 1 in place; accumulate denom ----
#pragma unroll
        for (int nt = 0; nt < 16; nt++) {
            float u;
            u = acc_s[nt][0] + 1.f; acc_s[nt][0] = fmaf(u, u, 1.f);
            u = acc_s[nt][1] + 1.f; acc_s[nt][1] = fmaf(u, u, 1.f);
            u = acc_s[nt][2] + 1.f; acc_s[nt][2] = fmaf(u, u, 1.f);
            u = acc_s[nt][3] + 1.f; acc_s[nt][3] = fmaf(u, u, 1.f);
            if (nt & 1) {
                dn0b += acc_s[nt][0] + acc_s[nt][1];
                dn1b += acc_s[nt][2] + acc_s[nt][3];
            } else {
                dn0a += acc_s[nt][0] + acc_s[nt][1];
                dn1a += acc_s[nt][2] + acc_s[nt][3];
            }
        }

        // ---- O += P @ V : P via register repack (C-frag -> A-frag) ----
#pragma unroll
        for (int kc = 0; kc < 8; kc++) {
            uint32_t ap[4];
            ap[0] = packh2(acc_s[2 * kc    ][0], acc_s[2 * kc    ][1]);
            ap[1] = packh2(acc_s[2 * kc    ][2], acc_s[2 * kc    ][3]);
            ap[2] = packh2(acc_s[2 * kc + 1][0], acc_s[2 * kc + 1][1]);
            ap[3] = packh2(acc_s[2 * kc + 1][2], acc_s[2 * kc + 1][3]);
            uint32_t bv[4][4];
#pragma unroll
            for (int dp = 0; dp < 4; dp++)
                ldsm_x4_trans(bv[dp], swz(vbuf[buf],
                    (kc * 16 + (((lane >> 3) & 1) << 3) + (lane & 7)) * 128
                    + (dp * 16 + ((lane >> 4) << 3)) * 2));
#pragma unroll
            for (int nt = 0; nt < 8; nt++)
                mma_f16(acc_o[nt], ap, &bv[nt >> 1][(nt & 1) * 2]);
        }
    }

    // ---- finalize denom (full row within this warp) ----
    float dn0 = dn0a + dn0b;
    float dn1 = dn1a + dn1b;
    dn0 += __shfl_xor_sync(0xffffffffu, dn0, 1);
    dn0 += __shfl_xor_sync(0xffffffffu, dn0, 2);
    dn1 += __shfl_xor_sync(0xffffffffu, dn1, 1);
    dn1 += __shfl_xor_sync(0xffffffffu, dn1, 2);
    const float inv1 = 1.f / dn0;
    const float inv2 = 1.f / dn1;

    // ---- store fp16 ----
    const int r1 = pm0 + grp, r2 = r1 + 8;
#pragma unroll
    for (int nt = 0; nt < 8; nt++) {
        const int c = h * D_HEAD + nt * 8 + 2 * qd;
        const size_t base1 = (size_t)(b * N_TOK + row0 + r1) * C_DIM + c;
        const size_t base2 = (size_t)(b * N_TOK + row0 + r2) * C_DIM + c;
        *(__half2*)&out[base1] = __floats2half2_rn(acc_o[nt][0] * inv1, acc_o[nt][1] * inv1);
        *(__half2*)&out[base2] = __floats2half2_rn(acc_o[nt][2] * inv2, acc_o[nt][3] * inv2);
    }
}

// ============================================================
// launcher
// ============================================================
extern "C" void kernel_launch(void* const* d_in, const int* in_sizes, int n_in,
                              void* d_out, int out_size)
{
    const float* x      = (const float*)d_in[0];
    const float* w_qkv  = (const float*)d_in[1];
    const float* w_proj = (const float*)d_in[2];
    const float* b_proj = (const float*)d_in[3];
    float* out = (float*)d_out;

    __half *qkv_s, *attn_s, *xh_s, *wqkvT_s, *wprojT_s;
    cudaGetSymbolAddress((void**)&qkv_s,    g_qkv);
    cudaGetSymbolAddress((void**)&attn_s,   g_attn);
    cudaGetSymbolAddress((void**)&xh_s,     g_xh);
    cudaGetSymbolAddress((void**)&wqkvT_s,  g_wqkvT);
    cudaGetSymbolAddress((void**)&wprojT_s, g_wprojT);

    cudaFuncSetAttribute(gemm1_f16, cudaFuncAttributeMaxDynamicSharedMemorySize,
                         (int)G1_SMEM_BYTES);
    cudaFuncSetAttribute(gemm2_f16, cudaFuncAttributeMaxDynamicSharedMemorySize,
                         (int)G2_SMEM_BYTES);
    cudaFuncSetAttribute(attn_f16, cudaFuncAttributeMaxDynamicSharedMemorySize,
                         (int)ATTN_SMEM_BYTES);

    const int M = B_SZ * N_TOK;  // 8192

    // ---- fused pre-pass (single launch) ----
    prepass_kernel<<<PP_XBLKS + PP_WQBLKS + PP_WPBLKS, 256>>>(
        x, xh_s, w_qkv, wqkvT_s, w_proj, wprojT_s);

    // 1) qkv = x @ w_qkv  (fp16 out, Q cols pre-scaled) — BK=64, 3-stage
    gemm1_f16<<<dim3(3 * C_DIM / 128, M / 128), 128, G1_SMEM_BYTES>>>(
        xh_s, wqkvT_s, qkv_s, M, 3 * C_DIM, C_DIM);

    // 2) fused Taylor attention -> fp16
    attn_f16<<<dim3(N_TOK / QROWS, B_SZ * H_NUM), 128, ATTN_SMEM_BYTES>>>(qkv_s, attn_s);

    // 3) out = attn @ w_proj + b_proj  (fp32 out) — 256thr/64x32-warp
    gemm2_f16<<<dim3(C_DIM / 128, M / 128), 256, G2_SMEM_BYTES>>>(
        attn_s, wprojT_s, b_proj, out, M, C_DIM, C_DIM);
}